// round 5
// baseline (speedup 1.0000x reference)
#include <cuda_runtime.h>
#include <math.h>
#include <stdint.h>

#define Bk   128
#define Hk   512
#define Tk   1024
#define INk  8
#define OUTk 2

#define CLUSTER 8          // 8 j-slice CTAs per batch-group = 1 cluster
#define JB   8
#define BBL  16
#define HJ   64            // H / JB
#define BC   8             // B / BBL
#define NCTA 128
#define NTHR 512           // 16 warps
#define NW   16
#define STEPS (Tk - 1)

typedef unsigned long long ull;

// ---------------- shared memory (~221 KB) ----------------
struct __align__(16) Smem {
    ull   wt2[Hk / 2][HJ];     // W_rec slice, k-pair packed           128 KB
    float hbuf[2][BC][Hk];     // full h, double-buffered (DSMEM dst)   32 KB
    float red[NW][BC][HJ];     // per-warp K partials                   32 KB
    float hist[BC][HJ][8];     // 8-step h history                      16 KB
    float Win[HJ][INk];
    float bias[HJ];
    float Wk[OUTk][Hk];
    float bkey[OUTk];
    float x[2][BC][INk];
    float key0[BC];
    float kred[16][16];
    ull   mbar[JB][2];         // per-slice, per-parity barriers (count=1)
};

union F2U { ull u; float2 f; };

__device__ __forceinline__ void fma2(ull& d, ull a, ull b) {
    asm("fma.rn.f32x2 %0, %1, %2, %0;" : "+l"(d) : "l"(a), "l"(b));
}
__device__ __forceinline__ uint32_t smem_u32(const void* p) {
    uint32_t a;
    asm("{ .reg .u64 t; cvta.to.shared.u64 t, %1; cvt.u32.u64 %0, t; }" : "=r"(a) : "l"(p));
    return a;
}
__device__ __forceinline__ uint32_t mapa_rank(uint32_t laddr, uint32_t rank) {
    uint32_t r;
    asm("mapa.shared::cluster.u32 %0, %1, %2;" : "=r"(r) : "r"(laddr), "r"(rank));
    return r;
}
__device__ __forceinline__ void st_cluster_f32(uint32_t addr, float v) {
    asm volatile("st.shared::cluster.f32 [%0], %1;" :: "r"(addr), "f"(v) : "memory");
}
__device__ __forceinline__ void mbar_init(uint32_t mbar, uint32_t cnt) {
    asm volatile("mbarrier.init.shared.b64 [%0], %1;" :: "r"(mbar), "r"(cnt) : "memory");
}
__device__ __forceinline__ void mbar_arrive_remote(uint32_t localMbar, uint32_t rank) {
    asm volatile(
        "{ .reg .b32 ra;\n\t"
        "  mapa.shared::cluster.u32 ra, %0, %1;\n\t"
        "  mbarrier.arrive.release.cluster.shared::cluster.b64 _, [ra]; }"
        :: "r"(localMbar), "r"(rank) : "memory");
}
__device__ __forceinline__ void mbar_wait(uint32_t mbar, uint32_t parity) {
    uint32_t done;
    asm volatile(
        "{ .reg .pred p;\n\t"
        "  mbarrier.try_wait.parity.acquire.cluster.shared::cta.b64 p, [%1], %2, 0x989680;\n\t"
        "  selp.b32 %0, 1, 0, p; }"
        : "=r"(done) : "r"(mbar), "r"(parity) : "memory");
    while (!done) {
        asm volatile(
            "{ .reg .pred p;\n\t"
            "  mbarrier.try_wait.parity.acquire.cluster.shared::cta.b64 p, [%1], %2, 0x989680;\n\t"
            "  selp.b32 %0, 1, 0, p; }"
            : "=r"(done) : "r"(mbar), "r"(parity) : "memory");
    }
}
__device__ __forceinline__ void cluster_sync() {
    asm volatile("barrier.cluster.arrive.aligned;" ::: "memory");
    asm volatile("barrier.cluster.wait.aligned;"   ::: "memory");
}

__global__ void __launch_bounds__(NTHR, 1) __cluster_dims__(CLUSTER, 1, 1)
rnn_cluster_kernel(const float* __restrict__ inputs,   // [B][IN][T]
                   const float* __restrict__ W_in,     // [H][IN]
                   const float* __restrict__ b_in,
                   const float* __restrict__ W_rec,    // [H][H]
                   const float* __restrict__ b_rec,
                   const float* __restrict__ W_key,    // [OUT][H]
                   const float* __restrict__ b_key,
                   float* __restrict__ out)
{
    extern __shared__ char smraw[];
    Smem& s = *reinterpret_cast<Smem*>(smraw);

    const int tid = threadIdx.x;
    uint32_t rank;
    asm("mov.u32 %0, %%cluster_ctarank;" : "=r"(rank));
    const int jb  = (int)rank;               // slice id within cluster
    const int bb  = blockIdx.x / CLUSTER;    // batch-group
    const int jg0 = jb * HJ;
    const int bg0 = bb * BC;
    const bool keyCTA = (jb == 0);

    float* keysOut = out;                                             // [B][2][T]
    float* prsOut  = out + (size_t)Bk * 2 * Tk;                       // [B][4][T]
    float* hsOut   = out + (size_t)Bk * 2 * Tk + (size_t)Bk * 4 * Tk; // [B][H][T]

    // ---------------- one-time init ----------------
    {
        const float2* wr2 = reinterpret_cast<const float2*>(W_rec);
        for (int idx = tid; idx < HJ * (Hk / 2); idx += NTHR) {
            int j  = idx >> 8;
            int k2 = idx & 255;
            F2U u; u.f = wr2[(size_t)(jg0 + j) * (Hk / 2) + k2];
            s.wt2[k2][j] = u.u;
        }
    }
    for (int idx = tid; idx < HJ * INk; idx += NTHR) {
        int j = idx / INk, i = idx % INk;
        s.Win[j][i] = W_in[(jg0 + j) * INk + i];
    }
    for (int j = tid; j < HJ; j += NTHR)
        s.bias[j] = b_in[jg0 + j] + b_rec[jg0 + j];
    if (keyCTA) {
        for (int idx = tid; idx < OUTk * Hk; idx += NTHR)
            s.Wk[idx / Hk][idx % Hk] = W_key[idx];
        if (tid < OUTk) s.bkey[tid] = b_key[tid];
        if (tid < BC) s.key0[tid] = 1.0f;
        if (tid < BC * 2) {
            int b = tid >> 1, o = tid & 1;
            keysOut[(size_t)(bg0 + b) * 2 * Tk + (size_t)o * Tk + 0] = 0.f;
        }
        if (tid < BC * 4) {
            int b = tid >> 2, c = tid & 3;
            prsOut[(size_t)(bg0 + b) * 4 * Tk + (size_t)c * Tk + 0] = 0.f;
        }
    }
    // h[0] = 0 (local full copy) ; hist slot 0 = 0 ; barriers
    for (int o = tid; o < BC * Hk; o += NTHR)
        (&s.hbuf[0][0][0])[o] = 0.f;
    if (tid < BC * HJ) {
        int b = tid >> 6, j = tid & 63;
        s.hist[b][j][0] = 0.f;
    }
    if (tid == 0) {
        #pragma unroll
        for (int sl = 0; sl < JB; ++sl) {
            mbar_init(smem_u32(&s.mbar[sl][0]), 1);
            mbar_init(smem_u32(&s.mbar[sl][1]), 1);
        }
    }
    __syncthreads();
    cluster_sync();                 // barriers + zeroed hbuf visible cluster-wide

    const int w    = tid >> 5;
    const int lane = tid & 31;
    const int jgrp = lane & 15;          // j0 = 4*jgrp
    const int b0   = (lane >> 4) * 4;    // 0 or 4
    const int mySlice = w >> 1;          // slice this warp depends on

    // precomputed DSMEM scatter addresses: my h value -> hbuf[*][b][jg0+j] in all 8 CTAs
    uint32_t scat[CLUSTER];
    {
        int b = tid >> 6, j = tid & 63;
        uint32_t la = smem_u32(&s.hbuf[0][0][0]) + ((uint32_t)(b * Hk + jg0 + j) << 2);
        #pragma unroll
        for (int d = 0; d < CLUSTER; ++d) scat[d] = mapa_rank(la, d);
    }
    const uint32_t myBar0 = smem_u32(&s.mbar[jb][0]);
    const uint32_t myBar1 = smem_u32(&s.mbar[jb][1]);
    const uint32_t waitBar0 = smem_u32(&s.mbar[mySlice][0]);
    const uint32_t waitBar1 = smem_u32(&s.mbar[mySlice][1]);
    uint32_t ph0 = 0, ph1 = 0;   // per-warp parity trackers per buffer

    const ulonglong2* w2row = reinterpret_cast<const ulonglong2*>(&s.wt2[0][0]);

    // ================ time loop ================
    for (int st = 0; st < STEPS; ++st) {
        const int par  = st & 1;
        const int par1 = par ^ 1;

        // stage input column st+1 (consumed after sync1)
        if (tid < BC * INk) {
            int b = tid >> 3, i = tid & 7;
            s.x[par][b][i] = inputs[(size_t)(bg0 + b) * INk * Tk + (size_t)i * Tk + (st + 1)];
        }

        // ---- wait for my slice of h[st] (local mbarrier; st=0 is local zeros) ----
        if (st > 0) {
            if (par) { mbar_wait(waitBar1, ph1); if (lane == 0) {} ph1 ^= 1; }
            else     { mbar_wait(waitBar0, ph0); ph0 ^= 1; }
        }
        __syncwarp();

        // ---- matvec over this warp's 32-k slice (FFMA2) ----
        const ull* hU = reinterpret_cast<const ull*>(&s.hbuf[par][0][0]); // [b*256 + k2]
        ull acc[4][4];
        #pragma unroll
        for (int i = 0; i < 4; ++i)
            #pragma unroll
            for (int jj = 0; jj < 4; ++jj) acc[i][jj] = 0ull;

        #pragma unroll
        for (int kk2 = 0; kk2 < 16; ++kk2) {
            const int k2 = w * 16 + kk2;
            ulonglong2 wA = w2row[k2 * 32 + jgrp * 2];
            ulonglong2 wB = w2row[k2 * 32 + jgrp * 2 + 1];
            #pragma unroll
            for (int i = 0; i < 4; ++i) {
                ull hh = hU[(b0 + i) * 256 + k2];
                fma2(acc[i][0], wA.x, hh);
                fma2(acc[i][1], wA.y, hh);
                fma2(acc[i][2], wB.x, hh);
                fma2(acc[i][3], wB.y, hh);
            }
        }
        #pragma unroll
        for (int i = 0; i < 4; ++i) {
            float r[4];
            #pragma unroll
            for (int jj = 0; jj < 4; ++jj) {
                F2U u; u.u = acc[i][jj];
                r[jj] = u.f.x + u.f.y;
            }
            *reinterpret_cast<float4*>(&s.red[w][b0 + i][jgrp * 4]) =
                make_float4(r[0], r[1], r[2], r[3]);
        }
        __syncthreads();   // sync1: red ready, x staged, all warps done reading hbuf[par]

        // ---- finalize h[st+1], DSMEM scatter to all 8 CTAs' hbuf[par1] ----
        {
            int b = tid >> 6, j = tid & 63;
            float v = s.bias[j];
            #pragma unroll
            for (int ww = 0; ww < NW; ++ww) v += s.red[ww][b][j];
            #pragma unroll
            for (int i = 0; i < INk; ++i) v = fmaf(s.x[par][b][i], s.Win[j][i], v);
            float h = tanhf(v);
            s.hist[b][j][(st + 1) & 7] = h;
            const uint32_t off = (uint32_t)par1 * (BC * Hk * 4);
            #pragma unroll
            for (int d = 0; d < CLUSTER; ++d)
                st_cluster_f32(scat[d] + off, h);
        }
        // keyCTA: key partials from full h[st] (all slices present since before sync1)
        if (keyCTA && st >= 1 && tid < 256) {
            int p = tid >> 4, kg = tid & 15;
            int b = p >> 1, o = p & 1;
            float acck = 0.f;
            #pragma unroll
            for (int kk = 0; kk < 32; ++kk) {
                int k = kg * 32 + kk;
                acck = fmaf(s.hbuf[par][b][k], s.Wk[o][k], acck);
            }
            s.kred[p][kg] = acck;
        }
        __syncthreads();   // sync2: remote stores CTA-observed (drained), kred ready

        // ---- publish h[st+1]: one release-arrive per consumer ----
        if (tid < CLUSTER)
            mbar_arrive_remote(par1 ? myBar1 : myBar0, (uint32_t)tid);

        // ---- key head + pr (keyCTA, warp0) ----
        if (keyCTA) {
            if (st >= 1 && tid < 16) {
                int b2 = tid >> 1, o2 = tid & 1;
                float z = s.bkey[o2];
                #pragma unroll
                for (int g = 0; g < 16; ++g) z += s.kred[tid][g];
                float kv = 1.f / (1.f + expf(-z));
                keysOut[(size_t)(bg0 + b2) * 2 * Tk + (size_t)o2 * Tk + st] = kv;
                if (o2 == 0) s.key0[b2] = kv;
            }
            if (tid < 32) {
                __syncwarp();
                int b = tid >> 2, c = tid & 3;
                float kp = (st >= 1) ? s.key0[b] : 1.0f;
                float tm, arm;
                if (c < 2) { tm = s.x[par][b][6]; arm = s.x[par][b][c]; }
                else       { tm = s.x[par][b][7]; arm = s.x[par][b][c] * kp + s.x[par][b][c + 2] * (1.f - kp); }
                float d = (tm - arm) / (0.15f * arm);
                float v = (tm == 0.f) ? 0.f : d * d;
                prsOut[(size_t)(bg0 + b) * 4 * Tk + (size_t)c * Tk + (st + 1)] = v;
            }
        }

        // ---- flush 8-step history (same-thread slots) ----
        if (((st + 1) & 7) == 7) {
            const int base = st - 6;
            int b = tid >> 6, j = tid & 63;
            float4 lo = *reinterpret_cast<float4*>(&s.hist[b][j][0]);
            float4 hi = *reinterpret_cast<float4*>(&s.hist[b][j][4]);
            float* dst = &hsOut[(size_t)(bg0 + b) * Hk * Tk + (size_t)(jg0 + j) * Tk + base];
            *reinterpret_cast<float4*>(dst)     = lo;
            *reinterpret_cast<float4*>(dst + 4) = hi;
        }
    }

    // ================ epilogue: key(h[1023]) -> keys[:,:,1023] ================
    if (keyCTA) {
        // h[1023] lives in hbuf[1]; wait my slice's buf-1 barrier (last completion pending)
        mbar_wait(waitBar1, ph1);
        __syncthreads();
        if (tid < 256) {
            int p = tid >> 4, kg = tid & 15;
            int b = p >> 1, o = p & 1;
            float acck = 0.f;
            #pragma unroll
            for (int kk = 0; kk < 32; ++kk) {
                int k = kg * 32 + kk;
                acck = fmaf(s.hbuf[1][b][k], s.Wk[o][k], acck);
            }
            s.kred[p][kg] = acck;
        }
        __syncthreads();
        if (tid < 16) {
            int b2 = tid >> 1, o2 = tid & 1;
            float z = s.bkey[o2];
            #pragma unroll
            for (int g = 0; g < 16; ++g) z += s.kred[tid][g];
            float kv = 1.f / (1.f + expf(-z));
            keysOut[(size_t)(bg0 + b2) * 2 * Tk + (size_t)o2 * Tk + (Tk - 1)] = kv;
        }
    }

    // no CTA may exit while peers can still target its smem
    cluster_sync();
}

extern "C" void kernel_launch(void* const* d_in, const int* in_sizes, int n_in,
                              void* d_out, int out_size) {
    const float* inputs = (const float*)d_in[0];
    const float* W_in   = (const float*)d_in[1];
    const float* b_in   = (const float*)d_in[2];
    const float* W_rec  = (const float*)d_in[3];
    const float* b_rec  = (const float*)d_in[4];
    const float* W_key  = (const float*)d_in[5];
    const float* b_key  = (const float*)d_in[6];
    float* out = (float*)d_out;

    static bool attr_set = false;
    if (!attr_set) {
        cudaFuncSetAttribute(rnn_cluster_kernel,
                             cudaFuncAttributeMaxDynamicSharedMemorySize,
                             (int)sizeof(Smem));
        attr_set = true;
    }
    rnn_cluster_kernel<<<NCTA, NTHR, sizeof(Smem)>>>(
        inputs, W_in, b_in, W_rec, b_rec, W_key, b_key, out);
}

// round 6
// speedup vs baseline: 1.5341x; 1.5341x over previous
#include <cuda_runtime.h>
#include <math.h>
#include <stdint.h>

#define Bk   128
#define Hk   512
#define Tk   1024
#define INk  8
#define OUTk 2

#define JB   8          // j-slice CTAs per batch-group
#define BBL  16         // batch-groups
#define HJ   64         // H / JB
#define BC   8          // batches per CTA (total)
#define TB   4          // batches per team
#define NWT  8          // warps per team
#define NCTA 128
#define NTHR 512        // 16 warps = 2 teams
#define STEPS (Tk - 1)

typedef unsigned long long ull;

// ---------------- device globals ----------------
// h ping-pong: g_h[par][bb][team][jb][b_local*64 + j]   (2 MB, L2-resident)
__device__ float g_h[2][BBL][2][JB][TB * HJ];
__device__ int   g_flag[BBL][JB][2][8];      // [bb][jb][team][pad]: latest published step
__device__ unsigned g_count;                 // init barrier
__device__ volatile unsigned g_epoch;

// ---------------- shared memory (~184 KB) ----------------
struct __align__(16) Smem {
    ull   wt2[Hk / 2][HJ];        // W_rec slice, k-pair packed: (W[j][2k],W[j][2k+1])  128 KB
    float hbuf[2][TB][Hk];        // staged h per team                                   16 KB
    float red[2][NWT][TB][HJ];    // per-team per-warp K partials                        16 KB
    float hist[2][TB][HJ][8];     // 8-step h history per team                           16 KB
    float Win[HJ][INk];
    float bias[HJ];
    float Wk[OUTk][Hk];
    float bkey[OUTk];
    float x[2][2][TB][INk];       // [team][buf][b][i]
    float key0[2][TB];
    float kred[2][8][16];         // [team][b*2+o][kg]
};

union F2U { ull u; float2 f; };

__device__ __forceinline__ void fma2(ull& d, ull a, ull b) {
    asm("fma.rn.f32x2 %0, %1, %2, %0;" : "+l"(d) : "l"(a), "l"(b));
}
__device__ __forceinline__ int flag_acquire(const int* fp) {
    int v;
    asm volatile("ld.acquire.gpu.global.s32 %0, [%1];" : "=r"(v) : "l"(fp) : "memory");
    return v;
}
__device__ __forceinline__ void flag_release(int* fp, int v) {
    asm volatile("st.release.gpu.global.s32 [%0], %1;" :: "l"(fp), "r"(v) : "memory");
}
__device__ __forceinline__ void team_bar(int t) {
    asm volatile("bar.sync %0, %1;" :: "r"(1 + t), "r"(256) : "memory");
}
__device__ __forceinline__ void init_grid_barrier() {
    __syncthreads();
    if (threadIdx.x == 0) {
        __threadfence();
        unsigned e = g_epoch;
        if (atomicAdd(&g_count, 1u) == NCTA - 1u) {
            atomicExch(&g_count, 0u);
            __threadfence();
            g_epoch = e + 1u;
        } else {
            while (g_epoch == e) { }
            __threadfence();
        }
    }
    __syncthreads();
}

__global__ void __launch_bounds__(NTHR, 1)
rnn_team_kernel(const float* __restrict__ inputs,   // [B][IN][T]
                const float* __restrict__ W_in,     // [H][IN]
                const float* __restrict__ b_in,
                const float* __restrict__ W_rec,    // [H][H]
                const float* __restrict__ b_rec,
                const float* __restrict__ W_key,    // [OUT][H]
                const float* __restrict__ b_key,
                float* __restrict__ out)
{
    extern __shared__ char smraw[];
    Smem& s = *reinterpret_cast<Smem*>(smraw);

    const int tid = threadIdx.x;
    const int cta = blockIdx.x;
    const int jb  = cta % JB;
    const int bb  = cta / JB;
    const int jg0 = jb * HJ;
    const int bg0 = bb * BC;
    const bool keyCTA = (jb == 0);

    float* keysOut = out;                                             // [B][2][T]
    float* prsOut  = out + (size_t)Bk * 2 * Tk;                       // [B][4][T]
    float* hsOut   = out + (size_t)Bk * 2 * Tk + (size_t)Bk * 4 * Tk; // [B][H][T]

    // ---------------- one-time init (block-wide) ----------------
    {
        const float2* wr2 = reinterpret_cast<const float2*>(W_rec);
        for (int idx = tid; idx < HJ * (Hk / 2); idx += NTHR) {
            int j  = idx >> 8;
            int k2 = idx & 255;
            F2U u; u.f = wr2[(size_t)(jg0 + j) * (Hk / 2) + k2];
            s.wt2[k2][j] = u.u;
        }
    }
    for (int idx = tid; idx < HJ * INk; idx += NTHR) {
        int j = idx / INk, i = idx % INk;
        s.Win[j][i] = W_in[(jg0 + j) * INk + i];
    }
    for (int j = tid; j < HJ; j += NTHR)
        s.bias[j] = b_in[jg0 + j] + b_rec[jg0 + j];
    if (keyCTA) {
        for (int idx = tid; idx < OUTk * Hk; idx += NTHR)
            s.Wk[idx / Hk][idx % Hk] = W_key[idx];
        if (tid < OUTk) s.bkey[tid] = b_key[tid];
        if (tid < 2 * TB) s.key0[tid >> 2][tid & 3] = 1.0f;
        if (tid < BC * 2) {    // keys column 0 = 0
            int b = tid >> 1, o = tid & 1;
            keysOut[(size_t)(bg0 + b) * 2 * Tk + (size_t)o * Tk + 0] = 0.f;
        }
        if (tid < BC * 4) {    // prs column 0 = 0
            int b = tid >> 2, c = tid & 3;
            prsOut[(size_t)(bg0 + b) * 4 * Tk + (size_t)c * Tk + 0] = 0.f;
        }
    }
    // h[0] = 0 for both teams' slices; flags reset; hist slot 0 = 0
    for (int o = tid; o < 2 * TB * HJ; o += NTHR) {
        int t = o / (TB * HJ), r = o % (TB * HJ);
        g_h[0][bb][t][jb][r] = 0.f;
    }
    if (tid < 2) g_flag[bb][jb][tid][0] = 0;
    for (int o = tid; o < 2 * TB * HJ; o += NTHR) {
        int t = o / (TB * HJ), r = o % (TB * HJ);
        s.hist[t][r >> 6][r & 63][0] = 0.f;
    }
    __syncthreads();
    init_grid_barrier();     // all flags reset & h[0] visible grid-wide

    // ---------------- team decomposition ----------------
    const int t     = tid >> 8;            // team 0 / 1
    const int ttid  = tid & 255;           // tid within team
    const int wt    = ttid >> 5;           // warp within team (0..7): owns k-slice wt*64
    const int lane  = tid & 31;
    const int jgrp  = lane & 15;           // 4 j's: jgrp*4..
    const int bhalf = lane >> 4;           // 0/1: batches bhalf*2, bhalf*2+1

    int* myFlag   = &g_flag[bb][jb][t][0];
    const int* srcFlag = &g_flag[bb][wt][t][0];

    const ulonglong2* w2row = reinterpret_cast<const ulonglong2*>(&s.wt2[0][0]); // [k2*32 + jpair]
    const ull*        hU    = reinterpret_cast<const ull*>(&s.hbuf[t][0][0]);    // [b*256 + k2]

    // ================ time loop (per team, independent) ================
    for (int st = 0; st < STEPS; ++st) {
        const int par = st & 1;
        const int xp  = st & 1;

        // stage input column st+1 (team-local copy; consumed after bar1)
        if (ttid < TB * INk) {
            int b = ttid >> 3, i = ttid & 7;
            s.x[t][xp][b][i] =
                inputs[(size_t)(bg0 + t * TB + b) * INk * Tk + (size_t)i * Tk + (st + 1)];
        }

        // ---- per-warp: acquire-poll my k-slice's flag, stage 4 batches x 64 k ----
        {
            while (flag_acquire(srcFlag) < st) { }
            const float4* src = reinterpret_cast<const float4*>(&g_h[par][bb][t][wt][0]);
            #pragma unroll
            for (int r = 0; r < 2; ++r) {
                int q = lane + 32 * r;               // float4 idx 0..63
                float4 v = __ldcg(&src[q]);
                int b = q >> 4, j = (q & 15) * 4;
                *reinterpret_cast<float4*>(&s.hbuf[t][b][wt * 64 + j]) = v;
            }
            __syncwarp();
        }

        // ---- matvec: 64-k slice, 4 batches x 64 j (FFMA2) ----
        ull acc[2][4];
        #pragma unroll
        for (int i = 0; i < 2; ++i)
            #pragma unroll
            for (int jj = 0; jj < 4; ++jj) acc[i][jj] = 0ull;

        #pragma unroll 8
        for (int kk2 = 0; kk2 < 32; ++kk2) {
            const int k2 = wt * 32 + kk2;
            ulonglong2 wA = w2row[k2 * 32 + jgrp * 2];
            ulonglong2 wB = w2row[k2 * 32 + jgrp * 2 + 1];
            ull h0 = hU[(bhalf * 2 + 0) * 256 + k2];
            ull h1 = hU[(bhalf * 2 + 1) * 256 + k2];
            fma2(acc[0][0], wA.x, h0); fma2(acc[0][1], wA.y, h0);
            fma2(acc[0][2], wB.x, h0); fma2(acc[0][3], wB.y, h0);
            fma2(acc[1][0], wA.x, h1); fma2(acc[1][1], wA.y, h1);
            fma2(acc[1][2], wB.x, h1); fma2(acc[1][3], wB.y, h1);
        }
        #pragma unroll
        for (int i = 0; i < 2; ++i) {
            float r[4];
            #pragma unroll
            for (int jj = 0; jj < 4; ++jj) {
                F2U u; u.u = acc[i][jj];
                r[jj] = u.f.x + u.f.y;
            }
            *reinterpret_cast<float4*>(&s.red[t][wt][bhalf * 2 + i][jgrp * 4]) =
                make_float4(r[0], r[1], r[2], r[3]);
        }
        team_bar(t);     // bar1: red + hbuf + x staged (team-wide)

        // ---- finalize h[st+1] (256 outputs = team size) ----
        {
            int b = ttid >> 6, j = ttid & 63;
            float v = s.bias[j];
            #pragma unroll
            for (int ww = 0; ww < NWT; ++ww) v += s.red[t][ww][b][j];
            #pragma unroll
            for (int i = 0; i < INk; ++i) v = fmaf(s.x[t][xp][b][i], s.Win[j][i], v);
            float h = tanhf(v);
            g_h[par ^ 1][bb][t][jb][b * HJ + j] = h;
            s.hist[t][b][j][(st + 1) & 7] = h;
        }
        // keyCTA: key partials from hbuf = full h[st] of this team's batches
        if (keyCTA && st >= 1 && ttid < 128) {
            int p = ttid >> 4, kg = ttid & 15;    // p = b*2+o
            int b = p >> 1, o = p & 1;
            float acck = 0.f;
            #pragma unroll
            for (int kk = 0; kk < 32; ++kk) {
                int k = kg * 32 + kk;
                acck = fmaf(s.hbuf[t][b][k], s.Wk[o][k], acck);
            }
            s.kred[t][p][kg] = acck;
        }
        team_bar(t);     // bar2: h STGs + kred done (team-wide)

        // ---- publish this team's slice (release store; orders prior STGs via bar) ----
        if (ttid == 0) flag_release(myFlag, st + 1);

        // ---- keys + prs (keyCTA; first warp of team) ----
        if (keyCTA && ttid < 32) {
            if (st >= 1 && ttid < 8) {
                int b2 = ttid >> 1, o2 = ttid & 1;
                float z = s.bkey[o2];
                #pragma unroll
                for (int g = 0; g < 16; ++g) z += s.kred[t][ttid][g];
                float kv = 1.f / (1.f + expf(-z));
                keysOut[(size_t)(bg0 + t * TB + b2) * 2 * Tk + (size_t)o2 * Tk + st] = kv;
                if (o2 == 0) s.key0[t][b2] = kv;
            }
            __syncwarp();
            if (ttid < TB * 4) {
                int b = ttid >> 2, c = ttid & 3;
                float kp = s.key0[t][b];           // 1.0 at st=0 (init), else key[st-1]
                float tm, arm;
                if (c < 2) { tm = s.x[t][xp][b][6]; arm = s.x[t][xp][b][c]; }
                else       { tm = s.x[t][xp][b][7];
                             arm = s.x[t][xp][b][c] * kp + s.x[t][xp][b][c + 2] * (1.f - kp); }
                float d = (tm - arm) / (0.15f * arm);
                float v = (tm == 0.f) ? 0.f : d * d;
                prsOut[(size_t)(bg0 + t * TB + b) * 4 * Tk + (size_t)c * Tk + (st + 1)] = v;
            }
        }

        // ---- flush 8-step history (same-thread slots; after bar2) ----
        if (((st + 1) & 7) == 7) {
            const int base = st - 6;
            int b = ttid >> 6, j = ttid & 63;
            float4 lo = *reinterpret_cast<float4*>(&s.hist[t][b][j][0]);
            float4 hi = *reinterpret_cast<float4*>(&s.hist[t][b][j][4]);
            float* dst = &hsOut[(size_t)(bg0 + t * TB + b) * Hk * Tk +
                                (size_t)(jg0 + j) * Tk + base];
            *reinterpret_cast<float4*>(dst)     = lo;
            *reinterpret_cast<float4*>(dst + 4) = hi;
        }
    }

    // ================ epilogue: keys[:,:,1023] = sigmoid(Wk h[1023]) ================
    if (keyCTA) {
        {
            while (flag_acquire(srcFlag) < STEPS) { }
            const float4* src = reinterpret_cast<const float4*>(&g_h[STEPS & 1][bb][t][wt][0]);
            #pragma unroll
            for (int r = 0; r < 2; ++r) {
                int q = lane + 32 * r;
                float4 v = __ldcg(&src[q]);
                int b = q >> 4, j = (q & 15) * 4;
                *reinterpret_cast<float4*>(&s.hbuf[t][b][wt * 64 + j]) = v;
            }
        }
        team_bar(t);
        if (ttid < 128) {
            int p = ttid >> 4, kg = ttid & 15;
            int b = p >> 1, o = p & 1;
            float acck = 0.f;
            #pragma unroll
            for (int kk = 0; kk < 32; ++kk) {
                int k = kg * 32 + kk;
                acck = fmaf(s.hbuf[t][b][k], s.Wk[o][k], acck);
            }
            s.kred[t][p][kg] = acck;
        }
        team_bar(t);
        if (ttid < 8) {
            int b2 = ttid >> 1, o2 = ttid & 1;
            float z = s.bkey[o2];
            #pragma unroll
            for (int g = 0; g < 16; ++g) z += s.kred[t][ttid][g];
            float kv = 1.f / (1.f + expf(-z));
            keysOut[(size_t)(bg0 + t * TB + b2) * 2 * Tk + (size_t)o2 * Tk + (Tk - 1)] = kv;
        }
    }
}

extern "C" void kernel_launch(void* const* d_in, const int* in_sizes, int n_in,
                              void* d_out, int out_size) {
    const float* inputs = (const float*)d_in[0];
    const float* W_in   = (const float*)d_in[1];
    const float* b_in   = (const float*)d_in[2];
    const float* W_rec  = (const float*)d_in[3];
    const float* b_rec  = (const float*)d_in[4];
    const float* W_key  = (const float*)d_in[5];
    const float* b_key  = (const float*)d_in[6];
    float* out = (float*)d_out;

    static bool attr_set = false;
    if (!attr_set) {
        cudaFuncSetAttribute(rnn_team_kernel,
                             cudaFuncAttributeMaxDynamicSharedMemorySize,
                             (int)sizeof(Smem));
        attr_set = true;
    }
    rnn_team_kernel<<<NCTA, NTHR, sizeof(Smem)>>>(
        inputs, W_in, b_in, W_rec, b_rec, W_key, b_key, out);
}